// round 2
// baseline (speedup 1.0000x reference)
#include <cuda_runtime.h>
#include <cuda_bf16.h>

// RoiAlign: fm (1,256,50,50) f32, proposals (1024,4) f32 -> out (1024,256,7,7) f32
// Reference double-applies SCALE (1/16 twice => /256); roi_w/h clamp to >=1, so every
// box's sampled patch spans <=4 rows/cols -> separable fast path:
//   out[oy][ox] = sum_{y,x} Wy[oy][y] * Wx[ox][x] * patch[y][x]
// with Wy[oy][r] = 0.5 * sum over the bin's 2 subsamples of bilinear weight at row r.

#define C_CH  256
#define HH    50
#define WW    50
#define OUTSZ 7
#define SSAMP 14   // OUT * SR
#define SPAN  4    // max patch extent per axis for fast path

extern __shared__ float s_stage[];   // 256*49 floats = 50176 B (dynamic, opt-in)

__global__ __launch_bounds__(256, 4)
void roi_align_kernel(const float* __restrict__ fm,
                      const float* __restrict__ proposals,
                      float* __restrict__ out)
{
    const int n   = blockIdx.x;
    const int tid = threadIdx.x;

    // Unified axis arrays: Y samples at [0..13], X samples at [14..27]
    __shared__ float s_h[2 * SSAMP], s_l[2 * SSAMP];
    __shared__ int   s_a0[2 * SSAMP], s_a1[2 * SSAMP];
    __shared__ float sWy[OUTSZ][SPAN], sWx[OUTSZ][SPAN];
    __shared__ int   s_base[2];     // [0]=ybase, [1]=xbase
    __shared__ int   s_okArr[2];
    __shared__ int   s_yoff[SPAN];  // clamped row offsets (*WW)
    __shared__ int   s_xoff[SPAN];  // clamped col offsets

    // ---------- setup: warp 0 only, warp-level syncs ----------
    if (tid < 32) {
        if (tid < 2 * SSAMP) {
            const bool isY = tid < SSAMP;
            const int  s   = isY ? tid : tid - SSAMP;
            float4 p = reinterpret_cast<const float4*>(proposals)[n];
            const float sc = 0.0625f;
            float x1 = (p.x * sc) * sc, y1v = (p.y * sc) * sc;
            float x2 = (p.z * sc) * sc, y2v = (p.w * sc) * sc;
            float roiw = fmaxf(x2 - x1, 1.0f);
            float roih = fmaxf(y2v - y1v, 1.0f);
            float g = ((float)s + 0.5f) * 0.5f;              // (s+0.5)/SR
            float v = isY ? (y1v + (roih * (1.0f / 7.0f)) * g)
                          : (x1  + (roiw * (1.0f / 7.0f)) * g);
            const int L = isY ? HH : WW;                      // both 50
            bool valid = (v >= -1.0f) && (v <= (float)L);
            float vc = fminf(fmaxf(v, 0.0f), (float)(L - 1));
            int i0 = min((int)floorf(vc), L - 1);
            int i1 = min(i0 + 1, L - 1);
            float l = vc - (float)i0;
            float h = 1.0f - l;
            if (!valid) { h = 0.0f; l = 0.0f; }
            s_a0[tid] = i0; s_a1[tid] = i1; s_h[tid] = h; s_l[tid] = l;
        }
        __syncwarp();
        if (tid < 2) {   // per-axis bounds
            const int off = tid * SSAMP;
            int mn = 1 << 30, mx = -1;
            #pragma unroll
            for (int s = 0; s < SSAMP; s++) {
                mn = min(mn, s_a0[off + s]);
                mx = max(mx, s_a1[off + s]);
            }
            s_base[tid]  = mn;
            s_okArr[tid] = ((mx - mn) < SPAN) ? 1 : 0;
        }
        __syncwarp();
        if (tid < 2 * OUTSZ) {      // combined separable bin weights
            const bool isY = tid < OUTSZ;
            const int  o   = isY ? tid : tid - OUTSZ;
            const int  off = isY ? 0 : SSAMP;
            const int  base = s_base[isY ? 0 : 1];
            float w[SPAN] = {0.f, 0.f, 0.f, 0.f};
            #pragma unroll
            for (int k = 0; k < 2; k++) {
                int s = off + 2 * o + k;
                w[min(s_a0[s] - base, SPAN - 1)] += 0.5f * s_h[s];
                w[min(s_a1[s] - base, SPAN - 1)] += 0.5f * s_l[s];
            }
            #pragma unroll
            for (int j = 0; j < SPAN; j++) {
                if (isY) sWy[o][j] = w[j]; else sWx[o][j] = w[j];
            }
        } else if (tid < 2 * OUTSZ + SPAN) {
            int i = tid - 2 * OUTSZ;
            s_yoff[i] = min(s_base[0] + i, HH - 1) * WW;
        } else if (tid < 2 * OUTSZ + 2 * SPAN) {
            int i = tid - 2 * OUTSZ - SPAN;
            s_xoff[i] = min(s_base[1] + i, WW - 1);
        }
    }
    __syncthreads();

    const bool ok = (s_okArr[0] != 0) && (s_okArr[1] != 0);
    const float* fmc = fm + (size_t)tid * (HH * WW);

    if (ok) {
        // ---------- fast separable path: thread = channel ----------
        const int xo0 = s_xoff[0], xo1 = s_xoff[1], xo2 = s_xoff[2], xo3 = s_xoff[3];

        float r[SPAN][SPAN];
        #pragma unroll
        for (int y = 0; y < SPAN; y++) {
            const float* rp = fmc + s_yoff[y];
            r[y][0] = rp[xo0]; r[y][1] = rp[xo1]; r[y][2] = rp[xo2]; r[y][3] = rp[xo3];
        }

        float sx[SPAN][OUTSZ];
        #pragma unroll
        for (int o = 0; o < OUTSZ; o++) {
            float w0 = sWx[o][0], w1 = sWx[o][1], w2 = sWx[o][2], w3 = sWx[o][3];
            #pragma unroll
            for (int y = 0; y < SPAN; y++)
                sx[y][o] = r[y][0] * w0 + r[y][1] * w1 + r[y][2] * w2 + r[y][3] * w3;
        }

        float* st = s_stage + tid * 49;
        #pragma unroll
        for (int oy = 0; oy < OUTSZ; oy++) {
            float wy0 = sWy[oy][0], wy1 = sWy[oy][1], wy2 = sWy[oy][2], wy3 = sWy[oy][3];
            #pragma unroll
            for (int ox = 0; ox < OUTSZ; ox++)
                st[oy * 7 + ox] = wy0 * sx[0][ox] + wy1 * sx[1][ox]
                                + wy2 * sx[2][ox] + wy3 * sx[3][ox];
        }
    } else {
        // ---------- general fallback (block-uniform, direct global stores) ----------
        float* outc = out + ((size_t)n * C_CH + tid) * 49;
        for (int oy = 0; oy < OUTSZ; oy++) {
            for (int ox = 0; ox < OUTSZ; ox++) {
                float a = 0.0f;
                #pragma unroll
                for (int ky = 0; ky < 2; ky++) {
                    int sy = 2 * oy + ky;
                    int y0 = s_a0[sy] * WW, y1i = s_a1[sy] * WW;
                    float hy = s_h[sy], ly = s_l[sy];
                    #pragma unroll
                    for (int kx = 0; kx < 2; kx++) {
                        int sxi = SSAMP + 2 * ox + kx;
                        int x0 = s_a0[sxi], x1i = s_a1[sxi];
                        float hx = s_h[sxi], lx = s_l[sxi];
                        a += hy * (hx * fmc[y0 + x0]  + lx * fmc[y0 + x1i])
                           + ly * (hx * fmc[y1i + x0] + lx * fmc[y1i + x1i]);
                    }
                }
                outc[oy * 7 + ox] = a * 0.25f;
            }
        }
    }

    __syncthreads();

    if (ok) {
        // ---------- coalesced block-wide store: 3136 float4 ----------
        float4* dst = reinterpret_cast<float4*>(out + (size_t)n * (C_CH * 49));
        const float4* src = reinterpret_cast<const float4*>(s_stage);
        #pragma unroll
        for (int i = tid; i < (C_CH * 49) / 4; i += 256)
            dst[i] = src[i];
    }
}

extern "C" void kernel_launch(void* const* d_in, const int* in_sizes, int n_in,
                              void* d_out, int out_size) {
    const float* fm    = (const float*)d_in[0];   // (1,256,50,50) f32
    const float* props = (const float*)d_in[1];   // (1024,4) f32
    float* out         = (float*)d_out;           // (1024,256,7,7) f32
    int N = in_sizes[1] / 4;
    const int smem = C_CH * 49 * sizeof(float);   // 50176 B
    cudaFuncSetAttribute(roi_align_kernel,
                         cudaFuncAttributeMaxDynamicSharedMemorySize, smem);
    roi_align_kernel<<<N, 256, smem>>>(fm, props, out);
}